// round 2
// baseline (speedup 1.0000x reference)
#include <cuda_runtime.h>
#include <cuda_bf16.h>
#include <cstdint>

// Problem constants
#define BB      32
#define CC      256
#define HW      1024           // 32*32
#define NTOT    32768          // BB*HW
#define KK      1024
#define NQ      8388608        // BB*CC*HW

// Tiling
#define TN      64
#define TK      64
#define NTHREADS 256

// Scratch (no cudaMalloc allowed)
__device__ double g_loss;
__device__ int    g_idx[NTOT];
__device__ float  g_wnorm[KK];
__device__ float  g_zn2[NTOT];

// ---------------------------------------------------------------------------
// Kernel 1: ||w_k||^2 in double, rounded once to fp32 (order-insensitive:
// wn enters the final add against a ~256-magnitude term; 1e-10 error is
// far below the 3e-5 quantization step).
// ---------------------------------------------------------------------------
__global__ void wnorm_kernel(const float* __restrict__ w) {
    int k = blockIdx.x * 256 + threadIdx.x;
    const float* row = w + (size_t)k * CC;
    double s = 0.0;
    #pragma unroll 8
    for (int i = 0; i < CC; i++) { double v = (double)row[i]; s += v * v; }
    g_wnorm[k] = (float)s;
}

// ---------------------------------------------------------------------------
// Kernel 2: zn2[n] = fp32 sum of squares, emulating XLA:GPU vectorized row
// reduction (vector_size=2, 128 threads/row, warp shfl-down trees, masked
// cross-warp tree):
//   p_t = fl(fl(z[2t]^2) + fl(z[2t+1]^2)),  t in [0,128)
//   W_w = butterfly-tree over p[32w .. 32w+31]   (pairs l,l+16; l,l+8; ...)
//   zn2 = fl( fl(W0+W2) + fl(W1+W3) )
// One thread per row; rows are hw-consecutive so global reads coalesce.
// ---------------------------------------------------------------------------
__global__ void zn2_kernel(const float* __restrict__ z) {
    const int n  = blockIdx.x * NTHREADS + threadIdx.x;
    const int b  = n >> 10;
    const int hw = n & (HW - 1);
    const float* row = z + (size_t)b * (CC * HW) + hw;  // element d at row[d*HW]

    float W[4];
    #pragma unroll
    for (int w4 = 0; w4 < 4; w4++) {
        float p[32];
        #pragma unroll
        for (int l = 0; l < 32; l++) {
            float a = row[(size_t)(64 * w4 + 2 * l) * HW];
            float c = row[(size_t)(64 * w4 + 2 * l + 1) * HW];
            p[l] = __fadd_rn(__fmul_rn(a, a), __fmul_rn(c, c));
        }
        #pragma unroll
        for (int off = 16; off >= 1; off >>= 1)
            #pragma unroll
            for (int l = 0; l < 16; l++)
                if (l < off) p[l] = __fadd_rn(p[l], p[l + off]);
        W[w4] = p[0];
    }
    g_zn2[n] = __fadd_rn(__fadd_rn(W[0], W[2]), __fadd_rn(W[1], W[3]));
}

// ---------------------------------------------------------------------------
// Kernel 3: zero the loss accumulator
// ---------------------------------------------------------------------------
__global__ void init_kernel() { g_loss = 0.0; }

// ---------------------------------------------------------------------------
// Kernel 4: argmin over codes. One block per 64 consecutive n (same b).
// dot(n,k) is a single sequential fp32 FFMA chain over d = 0..255 ascending
// (cublas-sgemm-style). dist = fl(fl(zn2 - 2*dot) + wn), ties -> lowest k.
// Shared layout (floats): zs[256*64] | ws[256*66] | wn[1024] | zn[64]
// ---------------------------------------------------------------------------
__global__ __launch_bounds__(NTHREADS, 1)
void argmin_kernel(const float* __restrict__ z, const float* __restrict__ w) {
    extern __shared__ float sm[];
    float* zs = sm;                            // 16384 floats, row stride 64
    float* ws = sm + 16384;                    // 16896 floats, row stride 66
    float* wn = sm + 16384 + 16896;            // 1024 floats
    float* zn = sm + 16384 + 16896 + 1024;     // 64 floats

    const int t     = threadIdx.x;
    const int ntile = blockIdx.x;               // 0..511
    const int b     = ntile >> 4;
    const int hw0   = (ntile & 15) * TN;
    const float* zb = z + (size_t)b * (CC * HW) + hw0;

    // Load z tile: zs[d][n], coalesced
    {
        const int dl = t >> 6, nl = t & 63;
        #pragma unroll
        for (int d0 = 0; d0 < CC; d0 += 4)
            zs[(d0 + dl) * TN + nl] = zb[(size_t)(d0 + dl) * HW + nl];
        #pragma unroll
        for (int j = 0; j < 4; j++) wn[t * 4 + j] = g_wnorm[t * 4 + j];
        if (t < TN) zn[t] = g_zn2[ntile * TN + t];
    }
    __syncthreads();

    const int kl = t & 3, cg = t >> 2;          // w-tile load mapping
    const int ng = (t & 15) * 4;                // this thread's 4 n's
    const int kg = (t >> 4) * 4;                // this thread's 4 k's (per tile)

    const float zn0 = zn[ng], zn1 = zn[ng + 1], zn2v = zn[ng + 2], zn3 = zn[ng + 3];
    float znv[4] = {zn0, zn1, zn2v, zn3};

    float minv[4] = {1e30f, 1e30f, 1e30f, 1e30f};
    int   mini[4] = {0, 0, 0, 0};

    for (int kt = 0; kt < KK; kt += TK) {
        // Load + transpose w tile into ws[d][k] (stride 66 => conflict-free)
        #pragma unroll
        for (int klb = 0; klb < TK; klb += 4) {
            const int kk = klb + kl;
            float4 v = *(const float4*)&w[(size_t)(kt + kk) * CC + cg * 4];
            ws[(cg * 4 + 0) * 66 + kk] = v.x;
            ws[(cg * 4 + 1) * 66 + kk] = v.y;
            ws[(cg * 4 + 2) * 66 + kk] = v.z;
            ws[(cg * 4 + 3) * 66 + kk] = v.w;
        }
        __syncthreads();

        float acc[4][4] = {};
        #pragma unroll 8
        for (int d = 0; d < CC; d++) {
            float4 a   = *(const float4*)&zs[d * TN + ng];
            float2 b01 = *(const float2*)&ws[d * 66 + kg];
            float2 b23 = *(const float2*)&ws[d * 66 + kg + 2];
            float aa[4] = {a.x, a.y, a.z, a.w};
            float bb[4] = {b01.x, b01.y, b23.x, b23.y};
            #pragma unroll
            for (int j = 0; j < 4; j++)
                #pragma unroll
                for (int i = 0; i < 4; i++)
                    acc[j][i] = __fmaf_rn(aa[j], bb[i], acc[j][i]);
        }

        // dist exactly as reference: fl(fl(zn2 - 2*dot) + wn); ascending-k scan
        // with strict < keeps the lowest index on quantized ties.
        #pragma unroll
        for (int i = 0; i < 4; i++) {
            const int   kidx = kt + kg + i;
            const float wnv  = wn[kidx];
            #pragma unroll
            for (int j = 0; j < 4; j++) {
                float t1 = __fmaf_rn(-2.0f, acc[j][i], znv[j]);  // == fl(zn2 - 2*dot)
                float d2 = __fadd_rn(t1, wnv);
                if (d2 < minv[j]) { minv[j] = d2; mini[j] = kidx; }
            }
        }
        __syncthreads();
    }

    // Cross-thread reduction over the 16 k-groups sharing each n (reuse zs)
    float* rv = zs;                 // [16][64]
    int*   ri = (int*)(zs + 1024);  // [16][64]
    const int r = t >> 4;
    #pragma unroll
    for (int j = 0; j < 4; j++) {
        const int n = ng + j;
        rv[r * 64 + n] = minv[j];
        ri[r * 64 + n] = mini[j];
    }
    __syncthreads();
    if (t < 64) {
        float bv = rv[t];
        int   bi = ri[t];
        #pragma unroll
        for (int r2 = 1; r2 < 16; r2++) {
            float v  = rv[r2 * 64 + t];
            int   i2 = ri[r2 * 64 + t];
            if (v < bv || (v == bv && i2 < bi)) { bv = v; bi = i2; }
        }
        g_idx[ntile * TN + t] = bi;
    }
}

// ---------------------------------------------------------------------------
// Kernel 5: gather z_q into output + fused MSE accumulation (double)
// ---------------------------------------------------------------------------
__global__ void gather_kernel(const float* __restrict__ z,
                              const float* __restrict__ w,
                              float* __restrict__ out) {
    const int g  = blockIdx.x * NTHREADS + threadIdx.x;
    const int hw = g & (HW - 1);
    const int c  = (g >> 10) & (CC - 1);
    const int b  = g >> 18;
    const int idx = g_idx[(b << 10) + hw];
    const float v = __ldg(&w[(size_t)idx * CC + c]);
    out[g] = v;
    float d = z[g] - v;
    double s = (double)d * (double)d;
    #pragma unroll
    for (int o = 16; o; o >>= 1) s += __shfl_xor_sync(0xffffffffu, s, o);
    __shared__ double bs[8];
    const int lane = threadIdx.x & 31, wid = threadIdx.x >> 5;
    if (lane == 0) bs[wid] = s;
    __syncthreads();
    if (threadIdx.x == 0) {
        double tot = 0.0;
        #pragma unroll
        for (int i = 0; i < 8; i++) tot += bs[i];
        atomicAdd(&g_loss, tot);
    }
}

// ---------------------------------------------------------------------------
// Kernel 6: write the two loss scalars
// ---------------------------------------------------------------------------
__global__ void finalize_kernel(float* __restrict__ out, int out_size) {
    float loss = (float)(g_loss * (1.0 / (double)NQ));
    if (out_size >= NQ + 1) out[NQ] = loss;      // embedding_loss
    if (out_size >= NQ + 2) out[NQ + 1] = loss;  // commitment_loss (same value)
}

// ---------------------------------------------------------------------------
extern "C" void kernel_launch(void* const* d_in, const int* in_sizes, int n_in,
                              void* d_out, int out_size) {
    const float* z = (const float*)d_in[0];      // z_e: 32*256*32*32
    const float* w = (const float*)d_in[1];      // embed_weight: 1024*256
    float* out = (float*)d_out;

    const int smem = (16384 + 16896 + 1024 + 64) * (int)sizeof(float);
    cudaFuncSetAttribute(argmin_kernel, cudaFuncAttributeMaxDynamicSharedMemorySize, smem);

    wnorm_kernel<<<KK / 256, 256>>>(w);
    zn2_kernel<<<NTOT / NTHREADS, NTHREADS>>>(z);
    init_kernel<<<1, 1>>>();
    argmin_kernel<<<NTOT / TN, NTHREADS, smem>>>(z, w);
    gather_kernel<<<NQ / NTHREADS, NTHREADS>>>(z, w, out);
    finalize_kernel<<<1, 1>>>(out, out_size);
}

// round 3
// speedup vs baseline: 1.1089x; 1.1089x over previous
#include <cuda_runtime.h>
#include <cuda_bf16.h>
#include <cstdint>

// Problem constants
#define BB      32
#define CC      256
#define HW      1024           // 32*32
#define NTOT    32768          // BB*HW
#define KK      1024
#define NQ      8388608        // BB*CC*HW

#define TN      64             // n per block
#define TKC     64             // codes per tile
#define NKT     (KK / TKC)     // 16 code tiles
#define WPAD    260            // ws row stride in floats (k-major, d contiguous)
#define NTHREADS 256

// Scratch
__device__ double g_loss;
__device__ int    g_idx[NTOT];
__device__ float  g_wnorm[KK];
__device__ float  g_zn2[NTOT];

#define FFMA2(acc, a, b) \
    asm("fma.rn.f32x2 %0, %1, %2, %0;" : "+l"(acc) : "l"(a), "l"(b))
#define PACK2(out, lo, hi) \
    asm("mov.b64 %0, {%1, %2};" : "=l"(out) : "f"(lo), "f"(hi))
#define UNPACK2(lo, hi, in) \
    asm("mov.b64 {%0, %1}, %2;" : "=f"(lo), "=f"(hi) : "l"(in))
#define CP_ASYNC16(dst_u32, src_ptr) \
    asm volatile("cp.async.cg.shared.global [%0], [%1], 16;" :: "r"(dst_u32), "l"(src_ptr))
#define CP_COMMIT()  asm volatile("cp.async.commit_group;" ::: "memory")
#define CP_WAIT0()   asm volatile("cp.async.wait_group 0;" ::: "memory")

// ---------------------------------------------------------------------------
// Kernel 1: ||w_k||^2 in double, rounded once (order-insensitive vs 3e-5 plateau)
// ---------------------------------------------------------------------------
__global__ void wnorm_kernel(const float* __restrict__ w) {
    int k = blockIdx.x * 256 + threadIdx.x;
    const float* row = w + (size_t)k * CC;
    double s = 0.0;
    #pragma unroll 8
    for (int i = 0; i < CC; i++) { double v = (double)row[i]; s += v * v; }
    g_wnorm[k] = (float)s;
}

// ---------------------------------------------------------------------------
// Kernel 2: zn2[n] — exact XLA row-reduce emulation (vec=2, 4 warp trees,
// (W0+W2)+(W1+W3)). DO NOT CHANGE: bitwise-matched to reference (rel_err 0.0).
// ---------------------------------------------------------------------------
__global__ void zn2_kernel(const float* __restrict__ z) {
    const int n  = blockIdx.x * NTHREADS + threadIdx.x;
    const int b  = n >> 10;
    const int hw = n & (HW - 1);
    const float* row = z + (size_t)b * (CC * HW) + hw;

    float W[4];
    #pragma unroll
    for (int w4 = 0; w4 < 4; w4++) {
        float p[32];
        #pragma unroll
        for (int l = 0; l < 32; l++) {
            float a = row[(size_t)(64 * w4 + 2 * l) * HW];
            float c = row[(size_t)(64 * w4 + 2 * l + 1) * HW];
            p[l] = __fadd_rn(__fmul_rn(a, a), __fmul_rn(c, c));
        }
        #pragma unroll
        for (int off = 16; off >= 1; off >>= 1)
            #pragma unroll
            for (int l = 0; l < 16; l++)
                if (l < off) p[l] = __fadd_rn(p[l], p[l + off]);
        W[w4] = p[0];
    }
    g_zn2[n] = __fadd_rn(__fadd_rn(W[0], W[2]), __fadd_rn(W[1], W[3]));
}

__global__ void init_kernel() { g_loss = 0.0; }

// ---------------------------------------------------------------------------
// Kernel 3: argmin. Block = 64 n; 16 code-tiles of 64, cp.async double-buffered.
// Thread tile 4n x 4k; FFMA2 packs n-pairs; dot = ascending-d fp32 chain (exact).
// Shared (floats): zs[256*64]=16384 | ws0[64*260] | ws1[64*260] | wn[1024] | zn[64]
// ---------------------------------------------------------------------------
__global__ __launch_bounds__(NTHREADS, 1)
void argmin_kernel(const float* __restrict__ z, const float* __restrict__ w) {
    extern __shared__ float sm[];
    float* zs  = sm;                         // 16384
    float* ws0 = sm + 16384;                 // 16640
    float* ws1 = ws0 + TKC * WPAD;           // 16640
    float* wn  = ws1 + TKC * WPAD;           // 1024
    float* zn  = wn + KK;                    // 64

    const int t     = threadIdx.x;
    const int ntile = blockIdx.x;            // 0..511
    const int b     = ntile >> 4;
    const int hw0   = (ntile & 15) * TN;
    const float* zb = z + (size_t)b * (CC * HW) + hw0;

    uint32_t smem_u32;
    { uint64_t tmp; asm("cvta.to.shared.u64 %0, %1;" : "=l"(tmp) : "l"(sm));
      smem_u32 = (uint32_t)tmp; }
    const uint32_t ws_u32[2] = { smem_u32 + 16384u * 4u,
                                 smem_u32 + (16384u + TKC * WPAD) * 4u };

    // w-tile cp.async mapping: thread -> (kk row, quarter of the 256-f row)
    const int kk = t >> 2;            // 0..63
    const int qq = t & 3;             // 0..3

    // Prefetch code-tile 0 into ws0
    {
        const float* src = w + (size_t)kk * CC + qq * 64;
        uint32_t dst = ws_u32[0] + (uint32_t)(kk * WPAD + qq * 64) * 4u;
        #pragma unroll
        for (int j = 0; j < 16; j++)
            CP_ASYNC16(dst + j * 16u, src + j * 4);
        CP_COMMIT();
    }

    // Load z tile (zs[d][n], coalesced float4), wn, zn
    {
        #pragma unroll
        for (int j = 0; j < 16; j++) {
            int chunk = j * NTHREADS + t;
            int d  = chunk >> 4;
            int n4 = chunk & 15;
            *(float4*)&zs[d * TN + n4 * 4] = *(const float4*)&zb[(size_t)d * HW + n4 * 4];
        }
        #pragma unroll
        for (int j = 0; j < 4; j++) wn[t * 4 + j] = g_wnorm[t * 4 + j];
        if (t < TN) zn[t] = g_zn2[ntile * TN + t];
    }

    const int ng  = (t & 15) * 4;     // this thread's 4 n's
    const int kgl = (t >> 4) * 4;     // this thread's 4 local k's

    float minv[4] = {1e30f, 1e30f, 1e30f, 1e30f};
    int   mini[4] = {0, 0, 0, 0};
    float znv[4];

    const float* zsp = zs + ng;

    for (int kt = 0; kt < NKT; kt++) {
        CP_WAIT0();
        __syncthreads();
        if (kt == 0) {
            #pragma unroll
            for (int j = 0; j < 4; j++) znv[j] = zn[ng + j];
        }
        // Prefetch next code tile into the other buffer
        if (kt + 1 < NKT) {
            const float* src = w + (size_t)((kt + 1) * TKC + kk) * CC + qq * 64;
            uint32_t dst = ws_u32[(kt + 1) & 1] + (uint32_t)(kk * WPAD + qq * 64) * 4u;
            #pragma unroll
            for (int j = 0; j < 16; j++)
                CP_ASYNC16(dst + j * 16u, src + j * 4);
            CP_COMMIT();
        }

        const float* wsb = (kt & 1) ? ws1 : ws0;
        const float* wp  = wsb + kgl * WPAD;

        unsigned long long acc[2][4] = {};
        for (int d = 0; d < CC; d += 4) {
            float4 bv[4];
            #pragma unroll
            for (int i = 0; i < 4; i++)
                bv[i] = *(const float4*)(wp + i * WPAD + d);
            #pragma unroll
            for (int dd = 0; dd < 4; dd++) {
                unsigned long long a0 = *(const unsigned long long*)(zsp + (d + dd) * TN);
                unsigned long long a1 = *(const unsigned long long*)(zsp + (d + dd) * TN + 2);
                #pragma unroll
                for (int i = 0; i < 4; i++) {
                    float bsc = dd == 0 ? bv[i].x : dd == 1 ? bv[i].y : dd == 2 ? bv[i].z : bv[i].w;
                    unsigned long long b2;
                    PACK2(b2, bsc, bsc);
                    FFMA2(acc[0][i], a0, b2);
                    FFMA2(acc[1][i], a1, b2);
                }
            }
        }

        // dist = fl(fl(zn2 - 2*dot) + wn); ascending-k scan, strict < => lowest k
        #pragma unroll
        for (int i = 0; i < 4; i++) {
            const int   kidx = kt * TKC + kgl + i;
            const float wnv  = wn[kidx];
            float dn[4];
            UNPACK2(dn[0], dn[1], acc[0][i]);
            UNPACK2(dn[2], dn[3], acc[1][i]);
            #pragma unroll
            for (int j = 0; j < 4; j++) {
                float t1 = __fmaf_rn(-2.0f, dn[j], znv[j]);
                float d2 = __fadd_rn(t1, wnv);
                if (d2 < minv[j]) { minv[j] = d2; mini[j] = kidx; }
            }
        }
        __syncthreads();   // all done with wsb before it gets overwritten
    }

    // Cross-thread reduction over 16 k-groups per n (reuse zs area)
    float* rv = zs;                 // [16][64]
    int*   ri = (int*)(zs + 1024);  // [16][64]
    const int r = t >> 4;
    #pragma unroll
    for (int j = 0; j < 4; j++) {
        rv[r * 64 + ng + j] = minv[j];
        ri[r * 64 + ng + j] = mini[j];
    }
    __syncthreads();
    if (t < TN) {
        float bv = rv[t];
        int   bi = ri[t];
        #pragma unroll
        for (int r2 = 1; r2 < 16; r2++) {
            float v  = rv[r2 * 64 + t];
            int   i2 = ri[r2 * 64 + t];
            if (v < bv || (v == bv && i2 < bi)) { bv = v; bi = i2; }
        }
        g_idx[ntile * TN + t] = bi;
    }
}

// ---------------------------------------------------------------------------
// Kernel 4: gather z_q (float4) + fused MSE; ONE atomic per block
// ---------------------------------------------------------------------------
#define GBLOCKS 2048
__global__ void gather_kernel(const float* __restrict__ z,
                              const float* __restrict__ w,
                              float* __restrict__ out) {
    const int tid = blockIdx.x * NTHREADS + threadIdx.x;   // 524288 threads
    double s = 0.0;
    #pragma unroll
    for (int rep = 0; rep < 4; rep++) {
        const int e4 = tid + rep * (GBLOCKS * NTHREADS);
        const int g  = e4 * 4;
        const int hw = g & (HW - 1);
        const int c  = (g >> 10) & (CC - 1);
        const int b  = g >> 18;
        int4  iv = *(const int4*)(g_idx + (b << 10) + hw);
        float4 zv = *(const float4*)(z + g);
        float4 ov;
        ov.x = __ldg(&w[(size_t)iv.x * CC + c]);
        ov.y = __ldg(&w[(size_t)iv.y * CC + c]);
        ov.z = __ldg(&w[(size_t)iv.z * CC + c]);
        ov.w = __ldg(&w[(size_t)iv.w * CC + c]);
        *(float4*)(out + g) = ov;
        float dx = zv.x - ov.x, dy = zv.y - ov.y, dz = zv.z - ov.z, dw = zv.w - ov.w;
        s += (double)dx * dx + (double)dy * dy + (double)dz * dz + (double)dw * dw;
    }
    #pragma unroll
    for (int o = 16; o; o >>= 1) s += __shfl_xor_sync(0xffffffffu, s, o);
    __shared__ double bs[8];
    const int lane = threadIdx.x & 31, wid = threadIdx.x >> 5;
    if (lane == 0) bs[wid] = s;
    __syncthreads();
    if (threadIdx.x == 0) {
        double tot = 0.0;
        #pragma unroll
        for (int i = 0; i < 8; i++) tot += bs[i];
        atomicAdd(&g_loss, tot);
    }
}

__global__ void finalize_kernel(float* __restrict__ out, int out_size) {
    float loss = (float)(g_loss * (1.0 / (double)NQ));
    if (out_size >= NQ + 1) out[NQ] = loss;
    if (out_size >= NQ + 2) out[NQ + 1] = loss;
}

// ---------------------------------------------------------------------------
extern "C" void kernel_launch(void* const* d_in, const int* in_sizes, int n_in,
                              void* d_out, int out_size) {
    const float* z = (const float*)d_in[0];
    const float* w = (const float*)d_in[1];
    float* out = (float*)d_out;

    const int smem = (16384 + 2 * TKC * WPAD + KK + TN) * (int)sizeof(float); // 203008 B
    cudaFuncSetAttribute(argmin_kernel, cudaFuncAttributeMaxDynamicSharedMemorySize, smem);

    wnorm_kernel<<<KK / 256, 256>>>(w);
    zn2_kernel<<<NTOT / NTHREADS, NTHREADS>>>(z);
    init_kernel<<<1, 1>>>();
    argmin_kernel<<<NTOT / TN, NTHREADS, smem>>>(z, w);
    gather_kernel<<<GBLOCKS, NTHREADS>>>(z, w, out);
    finalize_kernel<<<1, 1>>>(out, out_size);
}